// round 6
// baseline (speedup 1.0000x reference)
#include <cuda_runtime.h>
#include <cstdint>

// FlattenHead: segmented row compaction.
// x: [B=16, T=4096, D=1024] fp32, seq_lens: [16] int32.
// out rows = concat of x[b, 0:seq_lens[b]] per batch.
//
// R6 = R3 winner (8 rows/block, 256 thr, occ 8, flat grid) + ONE change:
// evict-first streaming hints on both load and store streams.

static constexpr int B = 16;
static constexpr int T = 4096;
static constexpr int VEC_PER_ROW = 256;       // D/4 float4 per row
static constexpr int ROWS_PER_BLK = 8;
static constexpr int VECS_PER_BLK = ROWS_PER_BLK * VEC_PER_ROW;  // 2048
static constexpr int BLKS_PER_BATCH = T / ROWS_PER_BLK;           // 512

__device__ __forceinline__ float4 ldcs4(const float4* p) {
    float4 v;
    asm volatile("ld.global.cs.v4.f32 {%0,%1,%2,%3}, [%4];"
                 : "=f"(v.x), "=f"(v.y), "=f"(v.z), "=f"(v.w) : "l"(p));
    return v;
}
__device__ __forceinline__ void stcs4(float4* p, float4 v) {
    asm volatile("st.global.cs.v4.f32 [%0], {%1,%2,%3,%4};"
                 :: "l"(p), "f"(v.x), "f"(v.y), "f"(v.z), "f"(v.w) : "memory");
}

__global__ __launch_bounds__(256, 8)
void flatten_head_kernel(const float4* __restrict__ x,
                         const int* __restrict__ seq_lens,
                         float4* __restrict__ out)
{
    const int blk = blockIdx.x;
    const int b   = blk >> 9;                 // / BLKS_PER_BATCH
    const int t0  = (blk & (BLKS_PER_BATCH - 1)) * ROWS_PER_BLK;

    const int len = seq_lens[b];
    if (t0 >= len) return;                    // fully-invalid chunk

    // Exclusive prefix of lens[0..b-1], 32-bit (sum <= 65536).
    int prefix = 0;
#pragma unroll
    for (int i = 0; i < B; ++i)
        prefix += (i < b) ? seq_lens[i] : 0;

    const int tid = threadIdx.x;
    const float4* __restrict__ src = x   + ((b * T + t0) * VEC_PER_ROW);
    float4*       __restrict__ dst = out + ((prefix + t0) * VEC_PER_ROW);

    const int nvalid = min(len - t0, ROWS_PER_BLK) * VEC_PER_ROW;

    if (nvalid == VECS_PER_BLK) {
        // Fast path: front-batch streaming loads, then stores.
        float4 r[ROWS_PER_BLK];
#pragma unroll
        for (int k = 0; k < ROWS_PER_BLK; ++k)
            r[k] = ldcs4(src + tid + k * 256);
#pragma unroll
        for (int k = 0; k < ROWS_PER_BLK; ++k)
            stcs4(dst + tid + k * 256, r[k]);
    } else {
        // Boundary chunk (at most one per batch): predicated copy.
#pragma unroll
        for (int k = 0; k < ROWS_PER_BLK; ++k) {
            const int idx = tid + k * 256;
            if (idx < nvalid) stcs4(dst + idx, ldcs4(src + idx));
        }
    }
}

extern "C" void kernel_launch(void* const* d_in, const int* in_sizes, int n_in,
                              void* d_out, int out_size)
{
    (void)out_size;
    const float4* x;
    const int*    lens;
    if (in_sizes[0] == B) {                   // lens-first ordering (defensive)
        lens = (const int*)d_in[0];
        x    = (const float4*)((n_in > 1) ? d_in[1] : d_in[0]);
    } else {
        x    = (const float4*)d_in[0];
        lens = (const int*)((n_in > 1) ? d_in[1] : d_in[0]);
    }
    float4* out = (float4*)d_out;

    flatten_head_kernel<<<B * BLKS_PER_BATCH, 256>>>(x, lens, out);
}

// round 7
// speedup vs baseline: 1.0531x; 1.0531x over previous
#include <cuda_runtime.h>
#include <cstdint>

// FlattenHead: segmented row compaction.
// x: [B=16, T=4096, D=1024] fp32, seq_lens: [16] int32.
// out rows = concat of x[b, 0:seq_lens[b]] per batch.
//
// R7 = R3 config (256 thr, occ 8, plain ld/st, flat grid) with ROWS_PER_BLK
// 8 -> 16: 64KB per block, explicit 4-deep load/store groups (fits 32 regs).

static constexpr int B = 16;
static constexpr int T = 4096;
static constexpr int VEC_PER_ROW = 256;        // D/4 float4 per row
static constexpr int ROWS_PER_BLK = 16;
static constexpr int VECS_PER_BLK = ROWS_PER_BLK * VEC_PER_ROW;   // 4096
static constexpr int BLKS_PER_BATCH = T / ROWS_PER_BLK;           // 256
static constexpr int GROUP = 4;                // rows per ld/st group

__global__ __launch_bounds__(256, 8)
void flatten_head_kernel(const float4* __restrict__ x,
                         const int* __restrict__ seq_lens,
                         float4* __restrict__ out)
{
    const int blk = blockIdx.x;
    const int b   = blk >> 8;                  // / BLKS_PER_BATCH
    const int t0  = (blk & (BLKS_PER_BATCH - 1)) * ROWS_PER_BLK;

    const int len = seq_lens[b];
    if (t0 >= len) return;                     // fully-invalid chunk

    // Exclusive prefix of lens[0..b-1], 32-bit (sum <= 65536).
    int prefix = 0;
#pragma unroll
    for (int i = 0; i < B; ++i)
        prefix += (i < b) ? seq_lens[i] : 0;

    const int tid = threadIdx.x;
    const float4* __restrict__ src = x   + ((b * T + t0) * VEC_PER_ROW);
    float4*       __restrict__ dst = out + ((prefix + t0) * VEC_PER_ROW);

    const int nvalid = min(len - t0, ROWS_PER_BLK) * VEC_PER_ROW;

    if (nvalid == VECS_PER_BLK) {
        // Fast path: 4 groups of (4 loads, 4 stores) — matches 32-reg budget.
#pragma unroll
        for (int g = 0; g < ROWS_PER_BLK / GROUP; ++g) {
            float4 r[GROUP];
#pragma unroll
            for (int k = 0; k < GROUP; ++k)
                r[k] = src[tid + (g * GROUP + k) * 256];
#pragma unroll
            for (int k = 0; k < GROUP; ++k)
                dst[tid + (g * GROUP + k) * 256] = r[k];
        }
    } else {
        // Boundary chunk (at most one per batch): predicated copy.
#pragma unroll
        for (int k = 0; k < ROWS_PER_BLK; ++k) {
            const int idx = tid + k * 256;
            if (idx < nvalid) dst[idx] = src[idx];
        }
    }
}

extern "C" void kernel_launch(void* const* d_in, const int* in_sizes, int n_in,
                              void* d_out, int out_size)
{
    (void)out_size;
    const float4* x;
    const int*    lens;
    if (in_sizes[0] == B) {                    // lens-first ordering (defensive)
        lens = (const int*)d_in[0];
        x    = (const float4*)((n_in > 1) ? d_in[1] : d_in[0]);
    } else {
        x    = (const float4*)d_in[0];
        lens = (const int*)((n_in > 1) ? d_in[1] : d_in[0]);
    }
    float4* out = (float4*)d_out;

    flatten_head_kernel<<<B * BLKS_PER_BATCH, 256>>>(x, lens, out);
}

// round 8
// speedup vs baseline: 1.0540x; 1.0009x over previous
#include <cuda_runtime.h>
#include <cstdint>

// FlattenHead: segmented row compaction.
// x: [B=16, T=4096, D=1024] fp32, seq_lens: [16] int32.
// out rows = concat of x[b, 0:seq_lens[b]] per batch.
//
// R8 = R7 (16 rows/block, 256 thr, occ 8, 4-deep ld/st groups) + ONE change:
// loads go through the read-only (ld.global.nc) path.

static constexpr int B = 16;
static constexpr int T = 4096;
static constexpr int VEC_PER_ROW = 256;        // D/4 float4 per row
static constexpr int ROWS_PER_BLK = 16;
static constexpr int VECS_PER_BLK = ROWS_PER_BLK * VEC_PER_ROW;   // 4096
static constexpr int BLKS_PER_BATCH = T / ROWS_PER_BLK;           // 256
static constexpr int GROUP = 4;                // rows per ld/st group

__device__ __forceinline__ float4 ldnc4(const float4* p) {
    float4 v;
    asm volatile("ld.global.nc.v4.f32 {%0,%1,%2,%3}, [%4];"
                 : "=f"(v.x), "=f"(v.y), "=f"(v.z), "=f"(v.w) : "l"(p));
    return v;
}

__global__ __launch_bounds__(256, 8)
void flatten_head_kernel(const float4* __restrict__ x,
                         const int* __restrict__ seq_lens,
                         float4* __restrict__ out)
{
    const int blk = blockIdx.x;
    const int b   = blk >> 8;                  // / BLKS_PER_BATCH
    const int t0  = (blk & (BLKS_PER_BATCH - 1)) * ROWS_PER_BLK;

    const int len = seq_lens[b];
    if (t0 >= len) return;                     // fully-invalid chunk

    // Exclusive prefix of lens[0..b-1], 32-bit (sum <= 65536).
    int prefix = 0;
#pragma unroll
    for (int i = 0; i < B; ++i)
        prefix += (i < b) ? seq_lens[i] : 0;

    const int tid = threadIdx.x;
    const float4* __restrict__ src = x   + ((b * T + t0) * VEC_PER_ROW);
    float4*       __restrict__ dst = out + ((prefix + t0) * VEC_PER_ROW);

    const int nvalid = min(len - t0, ROWS_PER_BLK) * VEC_PER_ROW;

    if (nvalid == VECS_PER_BLK) {
        // Fast path: 4 groups of (4 nc-loads, 4 stores).
#pragma unroll
        for (int g = 0; g < ROWS_PER_BLK / GROUP; ++g) {
            float4 r[GROUP];
#pragma unroll
            for (int k = 0; k < GROUP; ++k)
                r[k] = ldnc4(src + tid + (g * GROUP + k) * 256);
#pragma unroll
            for (int k = 0; k < GROUP; ++k)
                dst[tid + (g * GROUP + k) * 256] = r[k];
        }
    } else {
        // Boundary chunk (at most one per batch): predicated copy.
#pragma unroll
        for (int k = 0; k < ROWS_PER_BLK; ++k) {
            const int idx = tid + k * 256;
            if (idx < nvalid) dst[idx] = ldnc4(src + idx);
        }
    }
}

extern "C" void kernel_launch(void* const* d_in, const int* in_sizes, int n_in,
                              void* d_out, int out_size)
{
    (void)out_size;
    const float4* x;
    const int*    lens;
    if (in_sizes[0] == B) {                    // lens-first ordering (defensive)
        lens = (const int*)d_in[0];
        x    = (const float4*)((n_in > 1) ? d_in[1] : d_in[0]);
    } else {
        x    = (const float4*)d_in[0];
        lens = (const int*)((n_in > 1) ? d_in[1] : d_in[0]);
    }
    float4* out = (float4*)d_out;

    flatten_head_kernel<<<B * BLKS_PER_BATCH, 256>>>(x, lens, out);
}